// round 11
// baseline (speedup 1.0000x reference)
#include <cuda_runtime.h>
#include <cstdint>

// ALNNLayer fused. thread = (k-group {4,3,3,3}) x (2 b) x (4 d, float4) — all loads LDG.128
// to beat the LSU dispatch floor (1.82 cyc/op/SM). Block = 128 thr (4 kg-warps x 2 bg x 16 dq).
// L-reduction via coalesced fp32 atomicAdd into a 213KB L2-resident accumulator.
// Shapes: X,T,M,DT: [B=64, L=200, D=64]; alpha: [K=13]; w_v,b_t: [K,L,D];
//         w_t: [K,L,D,4]; b_v: [K,1,D]; out: [B,K,D].
// Math per (b,k,l,d):
//   kern  = exp(-relu(alpha_k)*|T-4k|) = 2^(-|a*T + na|), a = relu(alpha)*log2e, na = -a*4k
//   inten = kern * relu(X)
//   lat   = relu(wt0*X + wt1*DT + wt2*inten + wt3*M + 4*b_t)
//   out[b,k,d] = relu( sum_l w_v*lat + 200*b_v[k,d] )

#define KREF 13
#define LN   200
#define DN   64
#define BN   64
#define LC   2
#define NCH  (LN / LC)          // 100
#define BTB  4                  // b per block
#define NBT  (BN / BTB)         // 16
#define BKD  (BN * KREF * DN)   // 53248
#define KT   4                  // max k's per k-group

// accumulator[b][k][d] — starts zero (static init); biaszero re-zeroes after reading.
__device__ __align__(16) float g_accum[BKD];

__device__ __forceinline__ float ex2f(float x) {
    float r; asm("ex2.approx.ftz.f32 %0, %1;" : "=f"(r) : "f"(x)); return r;
}

// lat = relu(wt . [x, dt, inten, m] + bt4) for one scalar element
__device__ __forceinline__ float elem(float4 wt, float xc, float tc, float mc,
                                      float dtc, float rxc, float btc,
                                      float ak, float nak)
{
    const float w  = fmaf(tc, ak, nak);
    const float e  = ex2f(-fabsf(w));      // 2^(-|w|)
    const float in = e * rxc;
    const float s  = fmaf(wt.x, xc,
                     fmaf(wt.y, dtc,
                     fmaf(wt.z, in,
                     fmaf(wt.w, mc, btc))));
    return fmaxf(s, 0.0f);
}

__global__ __launch_bounds__(128, 4)
void alnn_main(const float* __restrict__ X, const float* __restrict__ T,
               const float* __restrict__ M, const float* __restrict__ DT,
               const float* __restrict__ alpha,
               const float* __restrict__ w_v, const float* __restrict__ w_t,
               const float* __restrict__ b_t)
{
    const int chunk = blockIdx.x;            // 0..99
    const int btile = blockIdx.y;            // 0..15
    const int tid   = threadIdx.x;
    const int kg    = tid >> 5;              // warp id 0..3
    const int bg    = (tid >> 4) & 1;        // 0/1
    const int dq    = tid & 15;              // d-quad index
    const int d     = dq * 4;
    const int kbase = kg ? (3 * kg + 1) : 0; // 0,4,7,10
    const int kcnt  = kg ? 3 : 4;            // 4,3,3,3
    const int b0    = btile * BTB + bg * 2;  // this thread's first b
    const int l0    = chunk * LC;

    // per-k exp constants
    float a[KT], na[KT];
    #pragma unroll
    for (int kk = 0; kk < KT; kk++) {
        if (kk < kcnt) {
            const int k = kbase + kk;
            const float av = fmaxf(__ldg(alpha + k), 0.0f) * 1.4426950408889634f;
            a[kk]  = av;
            na[kk] = -av * (4.0f * (float)k);
        } else { a[kk] = 0.0f; na[kk] = 0.0f; }
    }

    float4 acc[KT][2];
    #pragma unroll
    for (int kk = 0; kk < KT; kk++)
        #pragma unroll
        for (int bi = 0; bi < 2; bi++)
            acc[kk][bi] = make_float4(0.f, 0.f, 0.f, 0.f);

    const size_t bstr = (size_t)LN * DN;

    #pragma unroll
    for (int li = 0; li < LC; li++) {
        const int l = l0 + li;
        const size_t ibase = (size_t)b0 * bstr + (size_t)l * DN + d;

        float4 x[2], t[2], m[2], dt[2], rx[2];
        #pragma unroll
        for (int bi = 0; bi < 2; bi++) {
            const size_t o = ibase + (size_t)bi * bstr;
            x[bi]  = __ldg(reinterpret_cast<const float4*>(X  + o));
            t[bi]  = __ldg(reinterpret_cast<const float4*>(T  + o));
            m[bi]  = __ldg(reinterpret_cast<const float4*>(M  + o));
            dt[bi] = __ldg(reinterpret_cast<const float4*>(DT + o));
            rx[bi].x = fmaxf(x[bi].x, 0.f);
            rx[bi].y = fmaxf(x[bi].y, 0.f);
            rx[bi].z = fmaxf(x[bi].z, 0.f);
            rx[bi].w = fmaxf(x[bi].w, 0.f);
        }

        #pragma unroll
        for (int kk = 0; kk < KT; kk++) {
            if (kk < kcnt) {
                const size_t woff = ((size_t)(kbase + kk) * LN + l) * DN + d;
                const float4 wv  = __ldg(reinterpret_cast<const float4*>(w_v + woff));
                const float4 btv = __ldg(reinterpret_cast<const float4*>(b_t + woff));
                const float4 bt4 = make_float4(4.f*btv.x, 4.f*btv.y, 4.f*btv.z, 4.f*btv.w);
                // wt[j] = features for d+j
                const float4* wtp = reinterpret_cast<const float4*>(w_t) + woff;
                const float4 wt0 = __ldg(wtp + 0);
                const float4 wt1 = __ldg(wtp + 1);
                const float4 wt2 = __ldg(wtp + 2);
                const float4 wt3 = __ldg(wtp + 3);
                const float ak = a[kk], nak = na[kk];

                #pragma unroll
                for (int bi = 0; bi < 2; bi++) {
                    acc[kk][bi].x = fmaf(wv.x,
                        elem(wt0, x[bi].x, t[bi].x, m[bi].x, dt[bi].x, rx[bi].x, bt4.x, ak, nak),
                        acc[kk][bi].x);
                    acc[kk][bi].y = fmaf(wv.y,
                        elem(wt1, x[bi].y, t[bi].y, m[bi].y, dt[bi].y, rx[bi].y, bt4.y, ak, nak),
                        acc[kk][bi].y);
                    acc[kk][bi].z = fmaf(wv.z,
                        elem(wt2, x[bi].z, t[bi].z, m[bi].z, dt[bi].z, rx[bi].z, bt4.z, ak, nak),
                        acc[kk][bi].z);
                    acc[kk][bi].w = fmaf(wv.w,
                        elem(wt3, x[bi].w, t[bi].w, m[bi].w, dt[bi].w, rx[bi].w, bt4.w, ak, nak),
                        acc[kk][bi].w);
                }
            }
        }
    }

    // coalesced fp32 reductions into the L2-resident accumulator
    #pragma unroll
    for (int kk = 0; kk < KT; kk++) {
        if (kk < kcnt) {
            #pragma unroll
            for (int bi = 0; bi < 2; bi++) {
                float* p = g_accum + ((size_t)(b0 + bi) * KREF + (kbase + kk)) * DN + d;
                atomicAdd(p + 0, acc[kk][bi].x);
                atomicAdd(p + 1, acc[kk][bi].y);
                atomicAdd(p + 2, acc[kk][bi].z);
                atomicAdd(p + 3, acc[kk][bi].w);
            }
        }
    }
}

// bias + relu epilogue; one scalar per thread (208 blocks). Re-zeroes accumulator.
__global__ __launch_bounds__(256)
void alnn_biaszero(const float* __restrict__ b_v, float* __restrict__ out)
{
    const int g = blockIdx.x * 256 + threadIdx.x;   // over BKD = 53248
    if (g >= BKD) return;
    const int d  = g & 63;
    const int k  = (g >> 6) % KREF;

    const float s  = g_accum[g];
    const float bv = __ldg(b_v + k * DN + d);
    out[g] = fmaxf(fmaf(200.f, bv, s), 0.f);
    g_accum[g] = 0.f;                               // ready for next call
}

extern "C" void kernel_launch(void* const* d_in, const int* in_sizes, int n_in,
                              void* d_out, int out_size)
{
    // metadata order: X, T, M, DT, alpha, w_v, w_t, b_v, b_t
    const float* X     = (const float*)d_in[0];
    const float* T     = (const float*)d_in[1];
    const float* M     = (const float*)d_in[2];
    const float* DT    = (const float*)d_in[3];
    const float* alpha = (const float*)d_in[4];
    const float* w_v   = (const float*)d_in[5];
    const float* w_t   = (const float*)d_in[6];
    const float* b_v   = (const float*)d_in[7];
    const float* b_t   = (const float*)d_in[8];
    float* out = (float*)d_out;

    dim3 grid(NCH, NBT);
    alnn_main<<<grid, 128>>>(X, T, M, DT, alpha, w_v, w_t, b_t);
    alnn_biaszero<<<(BKD + 255) / 256, 256>>>(b_v, out);
}

// round 12
// speedup vs baseline: 2.6328x; 2.6328x over previous
#include <cuda_runtime.h>
#include <cstdint>

// ALNNLayer fused. Proven r7 shape: thread = (k-group {7,6}) x (8 b) x (1 d), 128 thr,
// grid (50, 8) = 400 blocks, 3 blocks/SM. NEW: all per-l-step weight loads batched
// up-front (one latency hole per l-step instead of seven).
// L-reduction via coalesced fp32 atomicAdd into a 213KB L2-resident accumulator.
// Shapes: X,T,M,DT: [B=64, L=200, D=64]; alpha: [K=13]; w_v,b_t: [K,L,D];
//         w_t: [K,L,D,4]; b_v: [K,1,D]; out: [B,K,D].
// Math per (b,k,l,d):
//   kern  = exp(-relu(alpha_k)*|T-4k|) = 2^(-|a*T + na|), a = relu(alpha)*log2e, na = -a*4k
//   inten = kern * relu(X)
//   lat   = relu(wt0*X + wt1*DT + wt2*inten + wt3*M + 4*b_t)
//   out[b,k,d] = relu( sum_l w_v*lat + 200*b_v[k,d] )

#define KREF 13
#define LN   200
#define DN   64
#define BN   64
#define BT   8
#define LC   4
#define NCH  (LN / LC)          // 50
#define NBT  (BN / BT)          // 8
#define BKD  (BN * KREF * DN)   // 53248
#define KT   7                  // max k's per k-group

// accumulator[b][k][d] — starts zero (static init); biaszero re-zeroes after reading.
__device__ __align__(16) float g_accum[BKD];

__device__ __forceinline__ float ex2f(float x) {
    float r; asm("ex2.approx.ftz.f32 %0, %1;" : "=f"(r) : "f"(x)); return r;
}

__global__ __launch_bounds__(128, 3)
void alnn_main(const float* __restrict__ X, const float* __restrict__ T,
               const float* __restrict__ M, const float* __restrict__ DT,
               const float* __restrict__ alpha,
               const float* __restrict__ w_v, const float* __restrict__ w_t,
               const float* __restrict__ b_t)
{
    const int chunk = blockIdx.x;            // 0..49
    const int btile = blockIdx.y;            // 0..7
    const int warp  = threadIdx.x >> 5;      // 0..3
    const int lane  = threadIdx.x & 31;
    const int kg    = warp >> 1;             // 0/1
    const int dg    = warp & 1;              // 0/1
    const int d     = dg * 32 + lane;        // 0..63
    const int kbase = kg ? 7 : 0;
    const int kcnt  = kg ? 6 : 7;
    const int b0    = btile * BT;
    const int l0    = chunk * LC;

    // per-k exp constants
    float a[KT], na[KT];
    #pragma unroll
    for (int kk = 0; kk < KT; kk++) {
        if (kk < kcnt) {
            const int k = kbase + kk;
            const float av = fmaxf(__ldg(alpha + k), 0.0f) * 1.4426950408889634f;
            a[kk]  = av;
            na[kk] = -av * (4.0f * (float)k);
        } else { a[kk] = 0.0f; na[kk] = 0.0f; }
    }

    float acc[KT][BT];
    #pragma unroll
    for (int kk = 0; kk < KT; kk++)
        #pragma unroll
        for (int bi = 0; bi < BT; bi++) acc[kk][bi] = 0.0f;

    const size_t bstr = (size_t)LN * DN;

    #pragma unroll
    for (int li = 0; li < LC; li++) {
        const int l = l0 + li;

        // ---- batch ALL loads for this l-step first (max MLP, one latency hole) ----
        float  wv[KT], bt4[KT];
        float4 wt[KT];
        #pragma unroll
        for (int kk = 0; kk < KT; kk++) {
            if (kk < kcnt) {
                const size_t woff = ((size_t)(kbase + kk) * LN + l) * DN + d;
                wv[kk]  = __ldg(w_v + woff);
                bt4[kk] = __ldg(b_t + woff);
                wt[kk]  = __ldg(reinterpret_cast<const float4*>(w_t) + woff);
            }
        }

        const size_t ibase = (size_t)l * DN + d + (size_t)b0 * bstr;
        float x[BT], t[BT], m[BT], dt[BT], rx[BT];
        #pragma unroll
        for (int bi = 0; bi < BT; bi++) {
            const size_t o = ibase + (size_t)bi * bstr;
            x[bi]  = __ldg(X  + o);
            t[bi]  = __ldg(T  + o);
            m[bi]  = __ldg(M  + o);
            dt[bi] = __ldg(DT + o);
        }

        #pragma unroll
        for (int bi = 0; bi < BT; bi++) rx[bi] = fmaxf(x[bi], 0.0f);
        #pragma unroll
        for (int kk = 0; kk < KT; kk++)
            if (kk < kcnt) bt4[kk] *= 4.0f;

        // ---- compute ----
        #pragma unroll
        for (int kk = 0; kk < KT; kk++) {
            if (kk < kcnt) {
                const float ak = a[kk], nak = na[kk];
                const float4 w = wt[kk];
                const float wvk = wv[kk], btk = bt4[kk];

                #pragma unroll
                for (int bi = 0; bi < BT; bi++) {
                    const float ww = fmaf(t[bi], ak, nak);
                    const float e  = ex2f(-fabsf(ww));       // 2^(-|w|)
                    const float in = e * rx[bi];
                    const float s  = fmaf(w.x, x[bi],
                                     fmaf(w.y, dt[bi],
                                     fmaf(w.z, in,
                                     fmaf(w.w, m[bi], btk))));
                    acc[kk][bi] = fmaf(wvk, fmaxf(s, 0.0f), acc[kk][bi]);
                }
            }
        }
    }

    // coalesced fp32 reductions into the L2-resident accumulator
    #pragma unroll
    for (int kk = 0; kk < KT; kk++) {
        if (kk < kcnt) {
            #pragma unroll
            for (int bi = 0; bi < BT; bi++) {
                atomicAdd(&g_accum[((size_t)(b0 + bi) * KREF + (kbase + kk)) * DN + d],
                          acc[kk][bi]);
            }
        }
    }
}

// bias + relu epilogue; one scalar per thread (208 blocks). Re-zeroes accumulator.
__global__ __launch_bounds__(256)
void alnn_biaszero(const float* __restrict__ b_v, float* __restrict__ out)
{
    const int g = blockIdx.x * 256 + threadIdx.x;   // over BKD = 53248
    if (g >= BKD) return;
    const int d  = g & 63;
    const int k  = (g >> 6) % KREF;

    const float s  = g_accum[g];
    const float bv = __ldg(b_v + k * DN + d);
    out[g] = fmaxf(fmaf(200.f, bv, s), 0.f);
    g_accum[g] = 0.f;                               // ready for next call
}

extern "C" void kernel_launch(void* const* d_in, const int* in_sizes, int n_in,
                              void* d_out, int out_size)
{
    // metadata order: X, T, M, DT, alpha, w_v, w_t, b_v, b_t
    const float* X     = (const float*)d_in[0];
    const float* T     = (const float*)d_in[1];
    const float* M     = (const float*)d_in[2];
    const float* DT    = (const float*)d_in[3];
    const float* alpha = (const float*)d_in[4];
    const float* w_v   = (const float*)d_in[5];
    const float* w_t   = (const float*)d_in[6];
    const float* b_v   = (const float*)d_in[7];
    const float* b_t   = (const float*)d_in[8];
    float* out = (float*)d_out;

    dim3 grid(NCH, NBT);
    alnn_main<<<grid, 128>>>(X, T, M, DT, alpha, w_v, w_t, b_t);
    alnn_biaszero<<<(BKD + 255) / 256, 256>>>(b_v, out);
}